// round 7
// baseline (speedup 1.0000x reference)
#include <cuda_runtime.h>
#include <cstdint>

typedef unsigned long long ull;

#define MULQ 16
#define NPAIR 136
// packed-weight layout offsets (floats) inside g_W / sW  (identical to R3)
#define OFF_WA    0        // 136*2*16 = 4352 : per (p,half): 4x float4 {w0[2j],w0[2j+1],w110[2j],w110[2j+1]}
#define OFF_W112  4352     // 136*2*40 = 10880: per (p,half): 40 floats (wl*5+k), coeff-folded sym w112
#define OFF_W101  15232    // 16*2*16*8 = 4096: per (u,half,v): 8 floats (A101*w101)
#define W_TOTAL   19328

#define NT 448
#define NODES_PER_CTA 448
#define XS 452
#define SMEM_BYTES ((W_TOTAL + 64 * XS) * 4)

__device__ __align__(16) float g_W[W_TOTAL];

// ---------------- f32x2 helpers ----------------
__device__ __forceinline__ ull pack2(float a, float b) {
    ull r;
    asm("mov.b64 %0, {%1, %2};" : "=l"(r) : "f"(a), "f"(b));
    return r;
}
__device__ __forceinline__ void fma2(ull& acc, ull a, ull b) {
    asm("fma.rn.f32x2 %0, %1, %2, %0;" : "+l"(acc) : "l"(a), "l"(b));
}
__device__ __forceinline__ ull mul2(ull a, ull b) {
    ull r;
    asm("mul.rn.f32x2 %0, %1, %2;" : "=l"(r) : "l"(a), "l"(b));
    return r;
}
__device__ __forceinline__ ull add2(ull a, ull b) {
    ull r;
    asm("add.rn.f32x2 %0, %1, %2;" : "=l"(r) : "l"(a), "l"(b));
    return r;
}
__device__ __forceinline__ ull sub2(ull a, ull b) {
    ull r;
    asm("sub.rn.f32x2 %0, %1, %2;" : "=l"(r) : "l"(a), "l"(b));
    return r;
}
__device__ __forceinline__ float2 unpack2(ull v) {
    float2 r;
    asm("mov.b64 {%0, %1}, %2;" : "=f"(r.x), "=f"(r.y) : "l"(v));
    return r;
}

__device__ __forceinline__ void decode_pair(int p, int& u, int& v) {
    int uu = 0, r = p;
    while (r >= MULQ - uu) { r -= MULQ - uu; ++uu; }
    u = uu;
    v = uu + r;
}

// ---------------- weight prep (verbatim from R3, proven correct) ----------------
__global__ void prep_kernel(const float* __restrict__ w000, const float* __restrict__ w101,
                            const float* __restrict__ w110, const float* __restrict__ w112) {
    const float A000  = 0.044194173824159216f;
    const float A110  = 0.025515518153991442f;
    const float A101  = 0.0625f;
    const float S112A = 0.044194173824159216f;  // A112/sqrt(10)
    const float S112B = 0.025515518153991442f;  // A112/sqrt(30)

    const int tid = blockIdx.x * blockDim.x + threadIdx.x;
    const int nth = gridDim.x * blockDim.x;

    for (int idx = tid; idx < NPAIR * 32; idx += nth) {
        int p = idx >> 5, r = idx & 31;
        int half = r >> 4, q = r & 15;
        int j = q >> 2, pos = q & 3;
        int wl = 2 * j + (pos & 1);
        int w = half * 8 + wl;
        int u, v;
        decode_pair(p, u, v);
        const float* src = (pos >= 2) ? w110 : w000;
        float c = src[u * 256 + v * 16 + w];
        if (u != v) c += src[v * 256 + u * 16 + w];
        g_W[OFF_WA + idx] = c * ((pos >= 2) ? A110 : A000);
    }
    for (int idx = tid; idx < NPAIR * 80; idx += nth) {
        int p = idx / 80, r = idx - p * 80;
        int half = r / 40, f = r - half * 40;
        int wl = f / 5, k = f - 5 * wl;
        int w = half * 8 + wl;
        int u, v;
        decode_pair(p, u, v);
        float c = w112[u * 256 + v * 16 + w];
        if (u != v) c += w112[v * 256 + u * 16 + w];
        g_W[OFF_W112 + idx] = c * (k == 4 ? S112B : S112A);
    }
    for (int idx = tid; idx < 4096; idx += nth) {
        int u = idx >> 8, r = idx & 255;
        int half = r >> 7, v = (r >> 3) & 15, j = r & 7;
        int w = half * 8 + j;
        g_W[OFF_W101 + idx] = w101[u * 256 + v * 16 + w] * A101;
    }
}

// ---- main kernel: 448 thr, 448 nodes/CTA, thread = 2 nodes x 8 w (half), w-pair fma2 lanes ----
__global__ void __launch_bounds__(NT)
tsq_kernel(const float* __restrict__ nf, const float* __restrict__ nm,
           float* __restrict__ out, int nnodes) {
    extern __shared__ float smem[];
    float* sW = smem;
    float* sX = smem + W_TOTAL;
    const int t = threadIdx.x;

    // stage weights
    {
        const float4* src = (const float4*)g_W;
        float4* dst = (float4*)sW;
        for (int i = t; i < W_TOTAL / 4; i += NT) dst[i] = src[i];
    }
    // stage x = nf + nm, transposed: sX[comp * XS + node_local]
    {
        const int base4 = blockIdx.x * (NODES_PER_CTA * 16);
        const int limit4 = nnodes * 16;
        const float4* a4 = (const float4*)nf;
        const float4* b4 = (const float4*)nm;
        for (int i = t; i < NODES_PER_CTA * 16; i += NT) {
            int gi = base4 + i;
            float4 a = make_float4(0.f, 0.f, 0.f, 0.f), b = a;
            if (gi < limit4) { a = a4[gi]; b = b4[gi]; }
            int node = i >> 4, fq = (i & 15) << 2;
            sX[(fq + 0) * XS + node] = a.x + b.x;
            sX[(fq + 1) * XS + node] = a.y + b.y;
            sX[(fq + 2) * XS + node] = a.z + b.z;
            sX[(fq + 3) * XS + node] = a.w + b.w;
        }
    }
    __syncthreads();

    const int g   = t % 224;       // node group (224 groups x 2 nodes = 448)
    const int wh  = t / 224;       // w-half; 224 = 7 warps -> warp-uniform
    const int nl0 = g * 2;

    const float* xb = sX + nl0;

    // same fixed descriptors as R3 (ulonglong2 = 16B):
    const ulonglong2* WA = (const ulonglong2*)sW + wh * 4;                    // + p*8
    const ulonglong2* W2 = (const ulonglong2*)(sW + OFF_W112) + wh * 10;      // + p*20
    const ulonglong2* WQ = (const ulonglong2*)(sW + OFF_W101) + wh * 32;      // + u*64 + 2v

    ull acc0[8];   // [j(4)][node(2)] -> 2j+n ; lanes = w-pair (2j, 2j+1)
    ull acc2[40];  // [m(20)][node(2)] -> 2m+n ; lanes = local out2 floats (2m, 2m+1)
#pragma unroll
    for (int j = 0; j < 8; j++) acc0[j] = 0ull;
#pragma unroll
    for (int j = 0; j < 40; j++) acc2[j] = 0ull;

    int p = 0;
#pragma unroll 1
    for (int u = 0; u < MULQ; ++u) {
        const ull A0 = *(const ull*)(xb + u * XS);
        const ull AX = *(const ull*)(xb + (MULQ + 3 * u + 0) * XS);
        const ull AY = *(const ull*)(xb + (MULQ + 3 * u + 1) * XS);
        const ull AZ = *(const ull*)(xb + (MULQ + 3 * u + 2) * XS);
#pragma unroll 1
        for (int v = u; v < MULQ; ++v, ++p) {
            const ull B0 = *(const ull*)(xb + v * XS);
            const ull BX = *(const ull*)(xb + (MULQ + 3 * v + 0) * XS);
            const ull BY = *(const ull*)(xb + (MULQ + 3 * v + 1) * XS);
            const ull BZ = *(const ull*)(xb + (MULQ + 3 * v + 2) * XS);

            // basis, node-packed (lane = node)
            ull y   = mul2(A0, B0);
            ull m00 = mul2(AX, BX), m01 = mul2(AX, BY), m02 = mul2(AX, BZ);
            ull m10 = mul2(AY, BX), m11 = mul2(AY, BY), m12 = mul2(AY, BZ);
            ull m20 = mul2(AZ, BX), m21 = mul2(AZ, BY), m22 = mul2(AZ, BZ);
            ull h  = add2(m00, m11);
            ull sc = add2(h, m22);
            ull T0 = add2(m01, m10), T1 = add2(m02, m20), T2 = add2(m12, m21);
            ull T3 = sub2(m00, m11);
            ull T4 = sub2(add2(m22, m22), h);

            float2 fy = unpack2(y),  fs = unpack2(sc);
            float2 f0 = unpack2(T0), f1 = unpack2(T1), f2 = unpack2(T2);
            float2 f3 = unpack2(T3), f4 = unpack2(T4);

            // per-node operands
            ull yd0 = pack2(fy.x, fy.x), sd0 = pack2(fs.x, fs.x);
            ull yd1 = pack2(fy.y, fy.y), sd1 = pack2(fs.y, fs.y);
            ull t01_0 = pack2(f0.x, f1.x), t23_0 = pack2(f2.x, f3.x), t40_0 = pack2(f4.x, f0.x);
            ull t12_0 = pack2(f1.x, f2.x), t34_0 = pack2(f3.x, f4.x);
            ull t01_1 = pack2(f0.y, f1.y), t23_1 = pack2(f2.y, f3.y), t40_1 = pack2(f4.y, f0.y);
            ull t12_1 = pack2(f1.y, f2.y), t34_1 = pack2(f3.y, f4.y);

            const ulonglong2* wa = WA + p * 8;
            {
                ulonglong2 q0 = wa[0], q1 = wa[1], q2 = wa[2], q3 = wa[3];
                fma2(acc0[0], q0.x, yd0); fma2(acc0[1], q0.x, yd1);
                fma2(acc0[0], q0.y, sd0); fma2(acc0[1], q0.y, sd1);
                fma2(acc0[2], q1.x, yd0); fma2(acc0[3], q1.x, yd1);
                fma2(acc0[2], q1.y, sd0); fma2(acc0[3], q1.y, sd1);
                fma2(acc0[4], q2.x, yd0); fma2(acc0[5], q2.x, yd1);
                fma2(acc0[4], q2.y, sd0); fma2(acc0[5], q2.y, sd1);
                fma2(acc0[6], q3.x, yd0); fma2(acc0[7], q3.x, yd1);
                fma2(acc0[6], q3.y, sd0); fma2(acc0[7], q3.y, sd1);
            }
            const ulonglong2* w2 = W2 + p * 20;
            {
                ulonglong2 q;
                q = w2[0];
                fma2(acc2[0],  q.x, t01_0); fma2(acc2[1],  q.x, t01_1);
                fma2(acc2[2],  q.y, t23_0); fma2(acc2[3],  q.y, t23_1);
                q = w2[1];
                fma2(acc2[4],  q.x, t40_0); fma2(acc2[5],  q.x, t40_1);
                fma2(acc2[6],  q.y, t12_0); fma2(acc2[7],  q.y, t12_1);
                q = w2[2];
                fma2(acc2[8],  q.x, t34_0); fma2(acc2[9],  q.x, t34_1);
                fma2(acc2[10], q.y, t01_0); fma2(acc2[11], q.y, t01_1);
                q = w2[3];
                fma2(acc2[12], q.x, t23_0); fma2(acc2[13], q.x, t23_1);
                fma2(acc2[14], q.y, t40_0); fma2(acc2[15], q.y, t40_1);
                q = w2[4];
                fma2(acc2[16], q.x, t12_0); fma2(acc2[17], q.x, t12_1);
                fma2(acc2[18], q.y, t34_0); fma2(acc2[19], q.y, t34_1);
                q = w2[5];
                fma2(acc2[20], q.x, t01_0); fma2(acc2[21], q.x, t01_1);
                fma2(acc2[22], q.y, t23_0); fma2(acc2[23], q.y, t23_1);
                q = w2[6];
                fma2(acc2[24], q.x, t40_0); fma2(acc2[25], q.x, t40_1);
                fma2(acc2[26], q.y, t12_0); fma2(acc2[27], q.y, t12_1);
                q = w2[7];
                fma2(acc2[28], q.x, t34_0); fma2(acc2[29], q.x, t34_1);
                fma2(acc2[30], q.y, t01_0); fma2(acc2[31], q.y, t01_1);
                q = w2[8];
                fma2(acc2[32], q.x, t23_0); fma2(acc2[33], q.x, t23_1);
                fma2(acc2[34], q.y, t40_0); fma2(acc2[35], q.y, t40_1);
                q = w2[9];
                fma2(acc2[36], q.x, t12_0); fma2(acc2[37], q.x, t12_1);
                fma2(acc2[38], q.y, t34_0); fma2(acc2[39], q.y, t34_1);
            }
        }
    }

    // ---- store out0 + out2 now (frees 48 accs before out1) ----
    const int nodeBase = blockIdx.x * NODES_PER_CTA + nl0;
#pragma unroll
    for (int j = 0; j < 2; ++j) {
        const int node = nodeBase + j;
        if (node < nnodes) {
            float* dst = out + (size_t)node * 144;
            {
                float o0[8];
#pragma unroll
                for (int jj = 0; jj < 4; ++jj) {
                    float2 vv = unpack2(acc0[2 * jj + j]);
                    o0[2 * jj] = vv.x;
                    o0[2 * jj + 1] = vv.y;
                }
                float4* p0 = (float4*)(dst + wh * 8);
                p0[0] = make_float4(o0[0], o0[1], o0[2], o0[3]);
                p0[1] = make_float4(o0[4], o0[5], o0[6], o0[7]);
            }
            {
                float o2[40];
#pragma unroll
                for (int m = 0; m < 20; ++m) {
                    float2 vv = unpack2(acc2[2 * m + j]);
                    o2[2 * m] = vv.x;
                    o2[2 * m + 1] = vv.y;
                }
                float4* p2 = (float4*)(dst + 64 + wh * 40);
#pragma unroll
                for (int i = 0; i < 10; ++i)
                    p2[i] = make_float4(o2[4 * i], o2[4 * i + 1], o2[4 * i + 2], o2[4 * i + 3]);
            }
        }
    }

    // ---- out1 (8 w x 3 k x 2 nodes) ----
    ull acc1[24];  // [(jj*3+kk) (12)][node(2)]
#pragma unroll
    for (int j = 0; j < 24; j++) acc1[j] = 0ull;
#pragma unroll 1
    for (int u = 0; u < MULQ; ++u) {
        ull G[8];  // [jj(4)][node(2)], lanes = w-pair
#pragma unroll
        for (int j = 0; j < 8; j++) G[j] = 0ull;
        const ulonglong2* wq = WQ + u * 64;
#pragma unroll 4
        for (int v = 0; v < MULQ; ++v) {
            const ull X0 = *(const ull*)(xb + v * XS);
            float2 fx = unpack2(X0);
            ull xd0 = pack2(fx.x, fx.x), xd1 = pack2(fx.y, fx.y);
            ulonglong2 q0 = wq[2 * v], q1 = wq[2 * v + 1];
            fma2(G[0], q0.x, xd0); fma2(G[1], q0.x, xd1);
            fma2(G[2], q0.y, xd0); fma2(G[3], q0.y, xd1);
            fma2(G[4], q1.x, xd0); fma2(G[5], q1.x, xd1);
            fma2(G[6], q1.y, xd0); fma2(G[7], q1.y, xd1);
        }
        const ull K0 = *(const ull*)(xb + (MULQ + 3 * u + 0) * XS);
        const ull K1 = *(const ull*)(xb + (MULQ + 3 * u + 1) * XS);
        const ull K2 = *(const ull*)(xb + (MULQ + 3 * u + 2) * XS);
        float2 fk0 = unpack2(K0), fk1 = unpack2(K1), fk2 = unpack2(K2);
        ull k0d0 = pack2(fk0.x, fk0.x), k0d1 = pack2(fk0.y, fk0.y);
        ull k1d0 = pack2(fk1.x, fk1.x), k1d1 = pack2(fk1.y, fk1.y);
        ull k2d0 = pack2(fk2.x, fk2.x), k2d1 = pack2(fk2.y, fk2.y);
#pragma unroll
        for (int jj = 0; jj < 4; ++jj) {
            fma2(acc1[(jj * 3 + 0) * 2 + 0], G[2 * jj + 0], k0d0);
            fma2(acc1[(jj * 3 + 0) * 2 + 1], G[2 * jj + 1], k0d1);
            fma2(acc1[(jj * 3 + 1) * 2 + 0], G[2 * jj + 0], k1d0);
            fma2(acc1[(jj * 3 + 1) * 2 + 1], G[2 * jj + 1], k1d1);
            fma2(acc1[(jj * 3 + 2) * 2 + 0], G[2 * jj + 0], k2d0);
            fma2(acc1[(jj * 3 + 2) * 2 + 1], G[2 * jj + 1], k2d1);
        }
    }

    // ---- store out1 ----
#pragma unroll
    for (int j = 0; j < 2; ++j) {
        const int node = nodeBase + j;
        if (node < nnodes) {
            float* dst = out + (size_t)node * 144;
            float o1[24];
#pragma unroll
            for (int jj = 0; jj < 4; ++jj)
#pragma unroll
                for (int kk = 0; kk < 3; ++kk) {
                    float2 vv = unpack2(acc1[(jj * 3 + kk) * 2 + j]);
                    o1[(2 * jj) * 3 + kk] = vv.x;
                    o1[(2 * jj + 1) * 3 + kk] = vv.y;
                }
            float4* p1 = (float4*)(dst + 16 + wh * 24);
#pragma unroll
            for (int i = 0; i < 6; ++i)
                p1[i] = make_float4(o1[4 * i], o1[4 * i + 1], o1[4 * i + 2], o1[4 * i + 3]);
        }
    }
}

extern "C" void kernel_launch(void* const* d_in, const int* in_sizes, int n_in,
                              void* d_out, int out_size) {
    const float* nf   = (const float*)d_in[0];
    const float* nm   = (const float*)d_in[1];
    const float* w000 = (const float*)d_in[2];
    const float* w101 = (const float*)d_in[3];
    const float* w110 = (const float*)d_in[4];
    const float* w112 = (const float*)d_in[5];
    const int nnodes = in_sizes[0] / 64;

    prep_kernel<<<32, 256>>>(w000, w101, w110, w112);

    cudaFuncSetAttribute(tsq_kernel, cudaFuncAttributeMaxDynamicSharedMemorySize, SMEM_BYTES);
    const int grid = (nnodes + NODES_PER_CTA - 1) / NODES_PER_CTA;
    tsq_kernel<<<grid, NT, SMEM_BYTES>>>(nf, nm, (float*)d_out, nnodes);
}

// round 8
// speedup vs baseline: 1.5996x; 1.5996x over previous
#include <cuda_runtime.h>
#include <cstdint>

typedef unsigned long long ull;

#define MULQ 16
#define NPAIR 136
// packed-weight layout offsets (floats) inside g_W / sW  (identical to R3)
#define OFF_WA    0        // 136*2*16 = 4352 : per (p,half): 4x float4 {w0[2j],w0[2j+1],w110[2j],w110[2j+1]}
#define OFF_W112  4352     // 136*2*40 = 10880: per (p,half): 40 floats (wl*5+k), coeff-folded sym w112
#define OFF_W101  15232    // 16*2*16*8 = 4096: per (u,half,v): 8 floats (A101*w101)
#define W_TOTAL   19328

#define NT 448
#define NODES_PER_CTA 448
#define XS 452
#define SMEM_BYTES ((W_TOTAL + 64 * XS) * 4)

__device__ __align__(16) float g_W[W_TOTAL];

// ---------------- f32x2 helpers ----------------
__device__ __forceinline__ ull pack2(float a, float b) {
    ull r;
    asm("mov.b64 %0, {%1, %2};" : "=l"(r) : "f"(a), "f"(b));
    return r;
}
__device__ __forceinline__ void fma2(ull& acc, ull a, ull b) {
    asm("fma.rn.f32x2 %0, %1, %2, %0;" : "+l"(acc) : "l"(a), "l"(b));
}
__device__ __forceinline__ ull mul2(ull a, ull b) {
    ull r;
    asm("mul.rn.f32x2 %0, %1, %2;" : "=l"(r) : "l"(a), "l"(b));
    return r;
}
__device__ __forceinline__ ull add2(ull a, ull b) {
    ull r;
    asm("add.rn.f32x2 %0, %1, %2;" : "=l"(r) : "l"(a), "l"(b));
    return r;
}
__device__ __forceinline__ ull sub2(ull a, ull b) {
    ull r;
    asm("sub.rn.f32x2 %0, %1, %2;" : "=l"(r) : "l"(a), "l"(b));
    return r;
}
__device__ __forceinline__ float2 unpack2(ull v) {
    float2 r;
    asm("mov.b64 {%0, %1}, %2;" : "=f"(r.x), "=f"(r.y) : "l"(v));
    return r;
}

__device__ __forceinline__ void decode_pair(int p, int& u, int& v) {
    int uu = 0, r = p;
    while (r >= MULQ - uu) { r -= MULQ - uu; ++uu; }
    u = uu;
    v = uu + r;
}

// ---------------- weight prep (verbatim from R3, proven correct) ----------------
__global__ void prep_kernel(const float* __restrict__ w000, const float* __restrict__ w101,
                            const float* __restrict__ w110, const float* __restrict__ w112) {
    const float A000  = 0.044194173824159216f;
    const float A110  = 0.025515518153991442f;
    const float A101  = 0.0625f;
    const float S112A = 0.044194173824159216f;  // A112/sqrt(10)
    const float S112B = 0.025515518153991442f;  // A112/sqrt(30)

    const int tid = blockIdx.x * blockDim.x + threadIdx.x;
    const int nth = gridDim.x * blockDim.x;

    for (int idx = tid; idx < NPAIR * 32; idx += nth) {
        int p = idx >> 5, r = idx & 31;
        int half = r >> 4, q = r & 15;
        int j = q >> 2, pos = q & 3;
        int wl = 2 * j + (pos & 1);
        int w = half * 8 + wl;
        int u, v;
        decode_pair(p, u, v);
        const float* src = (pos >= 2) ? w110 : w000;
        float c = src[u * 256 + v * 16 + w];
        if (u != v) c += src[v * 256 + u * 16 + w];
        g_W[OFF_WA + idx] = c * ((pos >= 2) ? A110 : A000);
    }
    for (int idx = tid; idx < NPAIR * 80; idx += nth) {
        int p = idx / 80, r = idx - p * 80;
        int half = r / 40, f = r - half * 40;
        int wl = f / 5, k = f - 5 * wl;
        int w = half * 8 + wl;
        int u, v;
        decode_pair(p, u, v);
        float c = w112[u * 256 + v * 16 + w];
        if (u != v) c += w112[v * 256 + u * 16 + w];
        g_W[OFF_W112 + idx] = c * (k == 4 ? S112B : S112A);
    }
    for (int idx = tid; idx < 4096; idx += nth) {
        int u = idx >> 8, r = idx & 255;
        int half = r >> 7, v = (r >> 3) & 15, j = r & 7;
        int w = half * 8 + j;
        g_W[OFF_W101 + idx] = w101[u * 256 + v * 16 + w] * A101;
    }
}

// ---- main kernel: 448 thr, 448 nodes/CTA, thread = 2 nodes x 8 w (half), w-pair fma2 lanes ----
__global__ void __launch_bounds__(NT)
tsq_kernel(const float* __restrict__ nf, const float* __restrict__ nm,
           float* __restrict__ out, int nnodes) {
    extern __shared__ float smem[];
    float* sW = smem;
    float* sX = smem + W_TOTAL;
    const int t = threadIdx.x;

    // stage weights
    {
        const float4* src = (const float4*)g_W;
        float4* dst = (float4*)sW;
        for (int i = t; i < W_TOTAL / 4; i += NT) dst[i] = src[i];
    }
    // stage x = nf + nm, transposed: sX[comp * XS + node_local]
    {
        const int base4 = blockIdx.x * (NODES_PER_CTA * 16);
        const int limit4 = nnodes * 16;
        const float4* a4 = (const float4*)nf;
        const float4* b4 = (const float4*)nm;
        for (int i = t; i < NODES_PER_CTA * 16; i += NT) {
            int gi = base4 + i;
            float4 a = make_float4(0.f, 0.f, 0.f, 0.f), b = a;
            if (gi < limit4) { a = a4[gi]; b = b4[gi]; }
            int node = i >> 4, fq = (i & 15) << 2;
            sX[(fq + 0) * XS + node] = a.x + b.x;
            sX[(fq + 1) * XS + node] = a.y + b.y;
            sX[(fq + 2) * XS + node] = a.z + b.z;
            sX[(fq + 3) * XS + node] = a.w + b.w;
        }
    }
    __syncthreads();

    const int g   = t % 224;       // node group (224 groups x 2 nodes = 448)
    const int wh  = t / 224;       // w-half; 224 = 7 warps -> warp-uniform
    const int nl0 = g * 2;

    const float* xb = sX + nl0;

    // same fixed descriptors as R3 (ulonglong2 = 16B):
    const ulonglong2* WA = (const ulonglong2*)sW + wh * 4;                    // + p*8
    const ulonglong2* W2 = (const ulonglong2*)(sW + OFF_W112) + wh * 10;      // + p*20
    const ulonglong2* WQ = (const ulonglong2*)(sW + OFF_W101) + wh * 32;      // + u*64 + 2v

    ull acc0[8];   // [j(4)][node(2)] -> 2j+n ; lanes = w-pair (2j, 2j+1)
    ull acc2[40];  // [m(20)][node(2)] -> 2m+n ; lanes = local out2 floats (2m, 2m+1)
#pragma unroll
    for (int j = 0; j < 8; j++) acc0[j] = 0ull;
#pragma unroll
    for (int j = 0; j < 40; j++) acc2[j] = 0ull;

    int p = 0;
#pragma unroll 1
    for (int u = 0; u < MULQ; ++u) {
        const ull A0 = *(const ull*)(xb + u * XS);
        const ull AX = *(const ull*)(xb + (MULQ + 3 * u + 0) * XS);
        const ull AY = *(const ull*)(xb + (MULQ + 3 * u + 1) * XS);
        const ull AZ = *(const ull*)(xb + (MULQ + 3 * u + 2) * XS);
#pragma unroll 1
        for (int v = u; v < MULQ; ++v, ++p) {
            const ull B0 = *(const ull*)(xb + v * XS);
            const ull BX = *(const ull*)(xb + (MULQ + 3 * v + 0) * XS);
            const ull BY = *(const ull*)(xb + (MULQ + 3 * v + 1) * XS);
            const ull BZ = *(const ull*)(xb + (MULQ + 3 * v + 2) * XS);

            // basis, node-packed (lane = node)
            ull y   = mul2(A0, B0);
            ull m00 = mul2(AX, BX), m01 = mul2(AX, BY), m02 = mul2(AX, BZ);
            ull m10 = mul2(AY, BX), m11 = mul2(AY, BY), m12 = mul2(AY, BZ);
            ull m20 = mul2(AZ, BX), m21 = mul2(AZ, BY), m22 = mul2(AZ, BZ);
            ull h  = add2(m00, m11);
            ull sc = add2(h, m22);
            ull T0 = add2(m01, m10), T1 = add2(m02, m20), T2 = add2(m12, m21);
            ull T3 = sub2(m00, m11);
            ull T4 = sub2(add2(m22, m22), h);

            float2 fy = unpack2(y),  fs = unpack2(sc);
            float2 f0 = unpack2(T0), f1 = unpack2(T1), f2 = unpack2(T2);
            float2 f3 = unpack2(T3), f4 = unpack2(T4);

            // per-node operands
            ull yd0 = pack2(fy.x, fy.x), sd0 = pack2(fs.x, fs.x);
            ull yd1 = pack2(fy.y, fy.y), sd1 = pack2(fs.y, fs.y);
            ull t01_0 = pack2(f0.x, f1.x), t23_0 = pack2(f2.x, f3.x), t40_0 = pack2(f4.x, f0.x);
            ull t12_0 = pack2(f1.x, f2.x), t34_0 = pack2(f3.x, f4.x);
            ull t01_1 = pack2(f0.y, f1.y), t23_1 = pack2(f2.y, f3.y), t40_1 = pack2(f4.y, f0.y);
            ull t12_1 = pack2(f1.y, f2.y), t34_1 = pack2(f3.y, f4.y);

            const ulonglong2* wa = WA + p * 8;
            {
                ulonglong2 q0 = wa[0], q1 = wa[1], q2 = wa[2], q3 = wa[3];
                fma2(acc0[0], q0.x, yd0); fma2(acc0[1], q0.x, yd1);
                fma2(acc0[0], q0.y, sd0); fma2(acc0[1], q0.y, sd1);
                fma2(acc0[2], q1.x, yd0); fma2(acc0[3], q1.x, yd1);
                fma2(acc0[2], q1.y, sd0); fma2(acc0[3], q1.y, sd1);
                fma2(acc0[4], q2.x, yd0); fma2(acc0[5], q2.x, yd1);
                fma2(acc0[4], q2.y, sd0); fma2(acc0[5], q2.y, sd1);
                fma2(acc0[6], q3.x, yd0); fma2(acc0[7], q3.x, yd1);
                fma2(acc0[6], q3.y, sd0); fma2(acc0[7], q3.y, sd1);
            }
            const ulonglong2* w2 = W2 + p * 20;
            {
                ulonglong2 q;
                q = w2[0];
                fma2(acc2[0],  q.x, t01_0); fma2(acc2[1],  q.x, t01_1);
                fma2(acc2[2],  q.y, t23_0); fma2(acc2[3],  q.y, t23_1);
                q = w2[1];
                fma2(acc2[4],  q.x, t40_0); fma2(acc2[5],  q.x, t40_1);
                fma2(acc2[6],  q.y, t12_0); fma2(acc2[7],  q.y, t12_1);
                q = w2[2];
                fma2(acc2[8],  q.x, t34_0); fma2(acc2[9],  q.x, t34_1);
                fma2(acc2[10], q.y, t01_0); fma2(acc2[11], q.y, t01_1);
                q = w2[3];
                fma2(acc2[12], q.x, t23_0); fma2(acc2[13], q.x, t23_1);
                fma2(acc2[14], q.y, t40_0); fma2(acc2[15], q.y, t40_1);
                q = w2[4];
                fma2(acc2[16], q.x, t12_0); fma2(acc2[17], q.x, t12_1);
                fma2(acc2[18], q.y, t34_0); fma2(acc2[19], q.y, t34_1);
                q = w2[5];
                fma2(acc2[20], q.x, t01_0); fma2(acc2[21], q.x, t01_1);
                fma2(acc2[22], q.y, t23_0); fma2(acc2[23], q.y, t23_1);
                q = w2[6];
                fma2(acc2[24], q.x, t40_0); fma2(acc2[25], q.x, t40_1);
                fma2(acc2[26], q.y, t12_0); fma2(acc2[27], q.y, t12_1);
                q = w2[7];
                fma2(acc2[28], q.x, t34_0); fma2(acc2[29], q.x, t34_1);
                fma2(acc2[30], q.y, t01_0); fma2(acc2[31], q.y, t01_1);
                q = w2[8];
                fma2(acc2[32], q.x, t23_0); fma2(acc2[33], q.x, t23_1);
                fma2(acc2[34], q.y, t40_0); fma2(acc2[35], q.y, t40_1);
                q = w2[9];
                fma2(acc2[36], q.x, t12_0); fma2(acc2[37], q.x, t12_1);
                fma2(acc2[38], q.y, t34_0); fma2(acc2[39], q.y, t34_1);
            }
        }
    }

    // ---- store out0 + out2 now (frees 48 accs before out1) ----
    const int nodeBase = blockIdx.x * NODES_PER_CTA + nl0;
#pragma unroll
    for (int j = 0; j < 2; ++j) {
        const int node = nodeBase + j;
        if (node < nnodes) {
            float* dst = out + (size_t)node * 144;
            {
                float o0[8];
#pragma unroll
                for (int jj = 0; jj < 4; ++jj) {
                    float2 vv = unpack2(acc0[2 * jj + j]);
                    o0[2 * jj] = vv.x;
                    o0[2 * jj + 1] = vv.y;
                }
                float4* p0 = (float4*)(dst + wh * 8);
                p0[0] = make_float4(o0[0], o0[1], o0[2], o0[3]);
                p0[1] = make_float4(o0[4], o0[5], o0[6], o0[7]);
            }
            {
                float o2[40];
#pragma unroll
                for (int m = 0; m < 20; ++m) {
                    float2 vv = unpack2(acc2[2 * m + j]);
                    o2[2 * m] = vv.x;
                    o2[2 * m + 1] = vv.y;
                }
                float4* p2 = (float4*)(dst + 64 + wh * 40);
#pragma unroll
                for (int i = 0; i < 10; ++i)
                    p2[i] = make_float4(o2[4 * i], o2[4 * i + 1], o2[4 * i + 2], o2[4 * i + 3]);
            }
        }
    }

    // ---- out1 (8 w x 3 k x 2 nodes) ----
    ull acc1[24];  // [(jj*3+kk) (12)][node(2)]
#pragma unroll
    for (int j = 0; j < 24; j++) acc1[j] = 0ull;
#pragma unroll 1
    for (int u = 0; u < MULQ; ++u) {
        ull G[8];  // [jj(4)][node(2)], lanes = w-pair
#pragma unroll
        for (int j = 0; j < 8; j++) G[j] = 0ull;
        const ulonglong2* wq = WQ + u * 64;
#pragma unroll 4
        for (int v = 0; v < MULQ; ++v) {
            const ull X0 = *(const ull*)(xb + v * XS);
            float2 fx = unpack2(X0);
            ull xd0 = pack2(fx.x, fx.x), xd1 = pack2(fx.y, fx.y);
            ulonglong2 q0 = wq[2 * v], q1 = wq[2 * v + 1];
            fma2(G[0], q0.x, xd0); fma2(G[1], q0.x, xd1);
            fma2(G[2], q0.y, xd0); fma2(G[3], q0.y, xd1);
            fma2(G[4], q1.x, xd0); fma2(G[5], q1.x, xd1);
            fma2(G[6], q1.y, xd0); fma2(G[7], q1.y, xd1);
        }
        const ull K0 = *(const ull*)(xb + (MULQ + 3 * u + 0) * XS);
        const ull K1 = *(const ull*)(xb + (MULQ + 3 * u + 1) * XS);
        const ull K2 = *(const ull*)(xb + (MULQ + 3 * u + 2) * XS);
        float2 fk0 = unpack2(K0), fk1 = unpack2(K1), fk2 = unpack2(K2);
        ull k0d0 = pack2(fk0.x, fk0.x), k0d1 = pack2(fk0.y, fk0.y);
        ull k1d0 = pack2(fk1.x, fk1.x), k1d1 = pack2(fk1.y, fk1.y);
        ull k2d0 = pack2(fk2.x, fk2.x), k2d1 = pack2(fk2.y, fk2.y);
#pragma unroll
        for (int jj = 0; jj < 4; ++jj) {
            fma2(acc1[(jj * 3 + 0) * 2 + 0], G[2 * jj + 0], k0d0);
            fma2(acc1[(jj * 3 + 0) * 2 + 1], G[2 * jj + 1], k0d1);
            fma2(acc1[(jj * 3 + 1) * 2 + 0], G[2 * jj + 0], k1d0);
            fma2(acc1[(jj * 3 + 1) * 2 + 1], G[2 * jj + 1], k1d1);
            fma2(acc1[(jj * 3 + 2) * 2 + 0], G[2 * jj + 0], k2d0);
            fma2(acc1[(jj * 3 + 2) * 2 + 1], G[2 * jj + 1], k2d1);
        }
    }

    // ---- store out1 ----
#pragma unroll
    for (int j = 0; j < 2; ++j) {
        const int node = nodeBase + j;
        if (node < nnodes) {
            float* dst = out + (size_t)node * 144;
            float o1[24];
#pragma unroll
            for (int jj = 0; jj < 4; ++jj)
#pragma unroll
                for (int kk = 0; kk < 3; ++kk) {
                    float2 vv = unpack2(acc1[(jj * 3 + kk) * 2 + j]);
                    o1[(2 * jj) * 3 + kk] = vv.x;
                    o1[(2 * jj + 1) * 3 + kk] = vv.y;
                }
            float4* p1 = (float4*)(dst + 16 + wh * 24);
#pragma unroll
            for (int i = 0; i < 6; ++i)
                p1[i] = make_float4(o1[4 * i], o1[4 * i + 1], o1[4 * i + 2], o1[4 * i + 3]);
        }
    }
}

extern "C" void kernel_launch(void* const* d_in, const int* in_sizes, int n_in,
                              void* d_out, int out_size) {
    const float* nf   = (const float*)d_in[0];
    const float* nm   = (const float*)d_in[1];
    const float* w000 = (const float*)d_in[2];
    const float* w101 = (const float*)d_in[3];
    const float* w110 = (const float*)d_in[4];
    const float* w112 = (const float*)d_in[5];
    const int nnodes = in_sizes[0] / 64;

    prep_kernel<<<32, 256>>>(w000, w101, w110, w112);

    cudaFuncSetAttribute(tsq_kernel, cudaFuncAttributeMaxDynamicSharedMemorySize, SMEM_BYTES);
    const int grid = (nnodes + NODES_PER_CTA - 1) / NODES_PER_CTA;
    tsq_kernel<<<grid, NT, SMEM_BYTES>>>(nf, nm, (float*)d_out, nnodes);
}

// round 9
// speedup vs baseline: 1.6000x; 1.0002x over previous
#include <cuda_runtime.h>
#include <cstdint>

typedef unsigned long long ull;

#define MULQ 16
#define NPAIR 136
// packed-weight layout offsets (floats) inside g_W / sW  (identical to R3)
#define OFF_WA    0        // 136*2*16 = 4352 : per (p,half): 4x float4 {w0[2j],w0[2j+1],w110[2j],w110[2j+1]}
#define OFF_W112  4352     // 136*2*40 = 10880: per (p,half): 40 floats (wl*5+k), coeff-folded sym w112
#define OFF_W101  15232    // 16*2*16*8 = 4096: per (u,half,v): 8 floats (A101*w101)
#define W_TOTAL   19328

#define NT 448
#define NODES_PER_CTA 448
#define XS 452
#define SMEM_BYTES ((W_TOTAL + 64 * XS) * 4)

__device__ __align__(16) float g_W[W_TOTAL];

// ---------------- f32x2 helpers ----------------
__device__ __forceinline__ ull pack2(float a, float b) {
    ull r;
    asm("mov.b64 %0, {%1, %2};" : "=l"(r) : "f"(a), "f"(b));
    return r;
}
__device__ __forceinline__ void fma2(ull& acc, ull a, ull b) {
    asm("fma.rn.f32x2 %0, %1, %2, %0;" : "+l"(acc) : "l"(a), "l"(b));
}
__device__ __forceinline__ ull mul2(ull a, ull b) {
    ull r;
    asm("mul.rn.f32x2 %0, %1, %2;" : "=l"(r) : "l"(a), "l"(b));
    return r;
}
__device__ __forceinline__ ull add2(ull a, ull b) {
    ull r;
    asm("add.rn.f32x2 %0, %1, %2;" : "=l"(r) : "l"(a), "l"(b));
    return r;
}
__device__ __forceinline__ ull sub2(ull a, ull b) {
    ull r;
    asm("sub.rn.f32x2 %0, %1, %2;" : "=l"(r) : "l"(a), "l"(b));
    return r;
}
__device__ __forceinline__ float2 unpack2(ull v) {
    float2 r;
    asm("mov.b64 {%0, %1}, %2;" : "=f"(r.x), "=f"(r.y) : "l"(v));
    return r;
}

__device__ __forceinline__ void decode_pair(int p, int& u, int& v) {
    int uu = 0, r = p;
    while (r >= MULQ - uu) { r -= MULQ - uu; ++uu; }
    u = uu;
    v = uu + r;
}

// ---------------- weight prep (verbatim from R3, proven correct) ----------------
__global__ void prep_kernel(const float* __restrict__ w000, const float* __restrict__ w101,
                            const float* __restrict__ w110, const float* __restrict__ w112) {
    const float A000  = 0.044194173824159216f;
    const float A110  = 0.025515518153991442f;
    const float A101  = 0.0625f;
    const float S112A = 0.044194173824159216f;  // A112/sqrt(10)
    const float S112B = 0.025515518153991442f;  // A112/sqrt(30)

    const int tid = blockIdx.x * blockDim.x + threadIdx.x;
    const int nth = gridDim.x * blockDim.x;

    for (int idx = tid; idx < NPAIR * 32; idx += nth) {
        int p = idx >> 5, r = idx & 31;
        int half = r >> 4, q = r & 15;
        int j = q >> 2, pos = q & 3;
        int wl = 2 * j + (pos & 1);
        int w = half * 8 + wl;
        int u, v;
        decode_pair(p, u, v);
        const float* src = (pos >= 2) ? w110 : w000;
        float c = src[u * 256 + v * 16 + w];
        if (u != v) c += src[v * 256 + u * 16 + w];
        g_W[OFF_WA + idx] = c * ((pos >= 2) ? A110 : A000);
    }
    for (int idx = tid; idx < NPAIR * 80; idx += nth) {
        int p = idx / 80, r = idx - p * 80;
        int half = r / 40, f = r - half * 40;
        int wl = f / 5, k = f - 5 * wl;
        int w = half * 8 + wl;
        int u, v;
        decode_pair(p, u, v);
        float c = w112[u * 256 + v * 16 + w];
        if (u != v) c += w112[v * 256 + u * 16 + w];
        g_W[OFF_W112 + idx] = c * (k == 4 ? S112B : S112A);
    }
    for (int idx = tid; idx < 4096; idx += nth) {
        int u = idx >> 8, r = idx & 255;
        int half = r >> 7, v = (r >> 3) & 15, j = r & 7;
        int w = half * 8 + j;
        g_W[OFF_W101 + idx] = w101[u * 256 + v * 16 + w] * A101;
    }
}

// ---- main kernel: 448 thr, 448 nodes/CTA, thread = 2 nodes x 8 w (half), w-pair fma2 lanes ----
__global__ void __launch_bounds__(NT)
tsq_kernel(const float* __restrict__ nf, const float* __restrict__ nm,
           float* __restrict__ out, int nnodes) {
    extern __shared__ float smem[];
    float* sW = smem;
    float* sX = smem + W_TOTAL;
    const int t = threadIdx.x;

    // stage weights
    {
        const float4* src = (const float4*)g_W;
        float4* dst = (float4*)sW;
        for (int i = t; i < W_TOTAL / 4; i += NT) dst[i] = src[i];
    }
    // stage x = nf + nm, transposed: sX[comp * XS + node_local]
    {
        const int base4 = blockIdx.x * (NODES_PER_CTA * 16);
        const int limit4 = nnodes * 16;
        const float4* a4 = (const float4*)nf;
        const float4* b4 = (const float4*)nm;
        for (int i = t; i < NODES_PER_CTA * 16; i += NT) {
            int gi = base4 + i;
            float4 a = make_float4(0.f, 0.f, 0.f, 0.f), b = a;
            if (gi < limit4) { a = a4[gi]; b = b4[gi]; }
            int node = i >> 4, fq = (i & 15) << 2;
            sX[(fq + 0) * XS + node] = a.x + b.x;
            sX[(fq + 1) * XS + node] = a.y + b.y;
            sX[(fq + 2) * XS + node] = a.z + b.z;
            sX[(fq + 3) * XS + node] = a.w + b.w;
        }
    }
    __syncthreads();

    const int g   = t % 224;       // node group (224 groups x 2 nodes = 448)
    const int wh  = t / 224;       // w-half; 224 = 7 warps -> warp-uniform
    const int nl0 = g * 2;

    const float* xb = sX + nl0;

    // same fixed descriptors as R3 (ulonglong2 = 16B):
    const ulonglong2* WA = (const ulonglong2*)sW + wh * 4;                    // + p*8
    const ulonglong2* W2 = (const ulonglong2*)(sW + OFF_W112) + wh * 10;      // + p*20
    const ulonglong2* WQ = (const ulonglong2*)(sW + OFF_W101) + wh * 32;      // + u*64 + 2v

    ull acc0[8];   // [j(4)][node(2)] -> 2j+n ; lanes = w-pair (2j, 2j+1)
    ull acc2[40];  // [m(20)][node(2)] -> 2m+n ; lanes = local out2 floats (2m, 2m+1)
#pragma unroll
    for (int j = 0; j < 8; j++) acc0[j] = 0ull;
#pragma unroll
    for (int j = 0; j < 40; j++) acc2[j] = 0ull;

    int p = 0;
#pragma unroll 1
    for (int u = 0; u < MULQ; ++u) {
        const ull A0 = *(const ull*)(xb + u * XS);
        const ull AX = *(const ull*)(xb + (MULQ + 3 * u + 0) * XS);
        const ull AY = *(const ull*)(xb + (MULQ + 3 * u + 1) * XS);
        const ull AZ = *(const ull*)(xb + (MULQ + 3 * u + 2) * XS);
#pragma unroll 1
        for (int v = u; v < MULQ; ++v, ++p) {
            const ull B0 = *(const ull*)(xb + v * XS);
            const ull BX = *(const ull*)(xb + (MULQ + 3 * v + 0) * XS);
            const ull BY = *(const ull*)(xb + (MULQ + 3 * v + 1) * XS);
            const ull BZ = *(const ull*)(xb + (MULQ + 3 * v + 2) * XS);

            // basis, node-packed (lane = node)
            ull y   = mul2(A0, B0);
            ull m00 = mul2(AX, BX), m01 = mul2(AX, BY), m02 = mul2(AX, BZ);
            ull m10 = mul2(AY, BX), m11 = mul2(AY, BY), m12 = mul2(AY, BZ);
            ull m20 = mul2(AZ, BX), m21 = mul2(AZ, BY), m22 = mul2(AZ, BZ);
            ull h  = add2(m00, m11);
            ull sc = add2(h, m22);
            ull T0 = add2(m01, m10), T1 = add2(m02, m20), T2 = add2(m12, m21);
            ull T3 = sub2(m00, m11);
            ull T4 = sub2(add2(m22, m22), h);

            float2 fy = unpack2(y),  fs = unpack2(sc);
            float2 f0 = unpack2(T0), f1 = unpack2(T1), f2 = unpack2(T2);
            float2 f3 = unpack2(T3), f4 = unpack2(T4);

            // per-node operands
            ull yd0 = pack2(fy.x, fy.x), sd0 = pack2(fs.x, fs.x);
            ull yd1 = pack2(fy.y, fy.y), sd1 = pack2(fs.y, fs.y);
            ull t01_0 = pack2(f0.x, f1.x), t23_0 = pack2(f2.x, f3.x), t40_0 = pack2(f4.x, f0.x);
            ull t12_0 = pack2(f1.x, f2.x), t34_0 = pack2(f3.x, f4.x);
            ull t01_1 = pack2(f0.y, f1.y), t23_1 = pack2(f2.y, f3.y), t40_1 = pack2(f4.y, f0.y);
            ull t12_1 = pack2(f1.y, f2.y), t34_1 = pack2(f3.y, f4.y);

            const ulonglong2* wa = WA + p * 8;
            {
                ulonglong2 q0 = wa[0], q1 = wa[1], q2 = wa[2], q3 = wa[3];
                fma2(acc0[0], q0.x, yd0); fma2(acc0[1], q0.x, yd1);
                fma2(acc0[0], q0.y, sd0); fma2(acc0[1], q0.y, sd1);
                fma2(acc0[2], q1.x, yd0); fma2(acc0[3], q1.x, yd1);
                fma2(acc0[2], q1.y, sd0); fma2(acc0[3], q1.y, sd1);
                fma2(acc0[4], q2.x, yd0); fma2(acc0[5], q2.x, yd1);
                fma2(acc0[4], q2.y, sd0); fma2(acc0[5], q2.y, sd1);
                fma2(acc0[6], q3.x, yd0); fma2(acc0[7], q3.x, yd1);
                fma2(acc0[6], q3.y, sd0); fma2(acc0[7], q3.y, sd1);
            }
            const ulonglong2* w2 = W2 + p * 20;
            {
                ulonglong2 q;
                q = w2[0];
                fma2(acc2[0],  q.x, t01_0); fma2(acc2[1],  q.x, t01_1);
                fma2(acc2[2],  q.y, t23_0); fma2(acc2[3],  q.y, t23_1);
                q = w2[1];
                fma2(acc2[4],  q.x, t40_0); fma2(acc2[5],  q.x, t40_1);
                fma2(acc2[6],  q.y, t12_0); fma2(acc2[7],  q.y, t12_1);
                q = w2[2];
                fma2(acc2[8],  q.x, t34_0); fma2(acc2[9],  q.x, t34_1);
                fma2(acc2[10], q.y, t01_0); fma2(acc2[11], q.y, t01_1);
                q = w2[3];
                fma2(acc2[12], q.x, t23_0); fma2(acc2[13], q.x, t23_1);
                fma2(acc2[14], q.y, t40_0); fma2(acc2[15], q.y, t40_1);
                q = w2[4];
                fma2(acc2[16], q.x, t12_0); fma2(acc2[17], q.x, t12_1);
                fma2(acc2[18], q.y, t34_0); fma2(acc2[19], q.y, t34_1);
                q = w2[5];
                fma2(acc2[20], q.x, t01_0); fma2(acc2[21], q.x, t01_1);
                fma2(acc2[22], q.y, t23_0); fma2(acc2[23], q.y, t23_1);
                q = w2[6];
                fma2(acc2[24], q.x, t40_0); fma2(acc2[25], q.x, t40_1);
                fma2(acc2[26], q.y, t12_0); fma2(acc2[27], q.y, t12_1);
                q = w2[7];
                fma2(acc2[28], q.x, t34_0); fma2(acc2[29], q.x, t34_1);
                fma2(acc2[30], q.y, t01_0); fma2(acc2[31], q.y, t01_1);
                q = w2[8];
                fma2(acc2[32], q.x, t23_0); fma2(acc2[33], q.x, t23_1);
                fma2(acc2[34], q.y, t40_0); fma2(acc2[35], q.y, t40_1);
                q = w2[9];
                fma2(acc2[36], q.x, t12_0); fma2(acc2[37], q.x, t12_1);
                fma2(acc2[38], q.y, t34_0); fma2(acc2[39], q.y, t34_1);
            }
        }
    }

    // ---- store out0 + out2 now (frees 48 accs before out1) ----
    const int nodeBase = blockIdx.x * NODES_PER_CTA + nl0;
#pragma unroll
    for (int j = 0; j < 2; ++j) {
        const int node = nodeBase + j;
        if (node < nnodes) {
            float* dst = out + (size_t)node * 144;
            {
                float o0[8];
#pragma unroll
                for (int jj = 0; jj < 4; ++jj) {
                    float2 vv = unpack2(acc0[2 * jj + j]);
                    o0[2 * jj] = vv.x;
                    o0[2 * jj + 1] = vv.y;
                }
                float4* p0 = (float4*)(dst + wh * 8);
                p0[0] = make_float4(o0[0], o0[1], o0[2], o0[3]);
                p0[1] = make_float4(o0[4], o0[5], o0[6], o0[7]);
            }
            {
                float o2[40];
#pragma unroll
                for (int m = 0; m < 20; ++m) {
                    float2 vv = unpack2(acc2[2 * m + j]);
                    o2[2 * m] = vv.x;
                    o2[2 * m + 1] = vv.y;
                }
                float4* p2 = (float4*)(dst + 64 + wh * 40);
#pragma unroll
                for (int i = 0; i < 10; ++i)
                    p2[i] = make_float4(o2[4 * i], o2[4 * i + 1], o2[4 * i + 2], o2[4 * i + 3]);
            }
        }
    }

    // ---- out1 (8 w x 3 k x 2 nodes) ----
    ull acc1[24];  // [(jj*3+kk) (12)][node(2)]
#pragma unroll
    for (int j = 0; j < 24; j++) acc1[j] = 0ull;
#pragma unroll 1
    for (int u = 0; u < MULQ; ++u) {
        ull G[8];  // [jj(4)][node(2)], lanes = w-pair
#pragma unroll
        for (int j = 0; j < 8; j++) G[j] = 0ull;
        const ulonglong2* wq = WQ + u * 64;
#pragma unroll 4
        for (int v = 0; v < MULQ; ++v) {
            const ull X0 = *(const ull*)(xb + v * XS);
            float2 fx = unpack2(X0);
            ull xd0 = pack2(fx.x, fx.x), xd1 = pack2(fx.y, fx.y);
            ulonglong2 q0 = wq[2 * v], q1 = wq[2 * v + 1];
            fma2(G[0], q0.x, xd0); fma2(G[1], q0.x, xd1);
            fma2(G[2], q0.y, xd0); fma2(G[3], q0.y, xd1);
            fma2(G[4], q1.x, xd0); fma2(G[5], q1.x, xd1);
            fma2(G[6], q1.y, xd0); fma2(G[7], q1.y, xd1);
        }
        const ull K0 = *(const ull*)(xb + (MULQ + 3 * u + 0) * XS);
        const ull K1 = *(const ull*)(xb + (MULQ + 3 * u + 1) * XS);
        const ull K2 = *(const ull*)(xb + (MULQ + 3 * u + 2) * XS);
        float2 fk0 = unpack2(K0), fk1 = unpack2(K1), fk2 = unpack2(K2);
        ull k0d0 = pack2(fk0.x, fk0.x), k0d1 = pack2(fk0.y, fk0.y);
        ull k1d0 = pack2(fk1.x, fk1.x), k1d1 = pack2(fk1.y, fk1.y);
        ull k2d0 = pack2(fk2.x, fk2.x), k2d1 = pack2(fk2.y, fk2.y);
#pragma unroll
        for (int jj = 0; jj < 4; ++jj) {
            fma2(acc1[(jj * 3 + 0) * 2 + 0], G[2 * jj + 0], k0d0);
            fma2(acc1[(jj * 3 + 0) * 2 + 1], G[2 * jj + 1], k0d1);
            fma2(acc1[(jj * 3 + 1) * 2 + 0], G[2 * jj + 0], k1d0);
            fma2(acc1[(jj * 3 + 1) * 2 + 1], G[2 * jj + 1], k1d1);
            fma2(acc1[(jj * 3 + 2) * 2 + 0], G[2 * jj + 0], k2d0);
            fma2(acc1[(jj * 3 + 2) * 2 + 1], G[2 * jj + 1], k2d1);
        }
    }

    // ---- store out1 ----
#pragma unroll
    for (int j = 0; j < 2; ++j) {
        const int node = nodeBase + j;
        if (node < nnodes) {
            float* dst = out + (size_t)node * 144;
            float o1[24];
#pragma unroll
            for (int jj = 0; jj < 4; ++jj)
#pragma unroll
                for (int kk = 0; kk < 3; ++kk) {
                    float2 vv = unpack2(acc1[(jj * 3 + kk) * 2 + j]);
                    o1[(2 * jj) * 3 + kk] = vv.x;
                    o1[(2 * jj + 1) * 3 + kk] = vv.y;
                }
            float4* p1 = (float4*)(dst + 16 + wh * 24);
#pragma unroll
            for (int i = 0; i < 6; ++i)
                p1[i] = make_float4(o1[4 * i], o1[4 * i + 1], o1[4 * i + 2], o1[4 * i + 3]);
        }
    }
}

extern "C" void kernel_launch(void* const* d_in, const int* in_sizes, int n_in,
                              void* d_out, int out_size) {
    const float* nf   = (const float*)d_in[0];
    const float* nm   = (const float*)d_in[1];
    const float* w000 = (const float*)d_in[2];
    const float* w101 = (const float*)d_in[3];
    const float* w110 = (const float*)d_in[4];
    const float* w112 = (const float*)d_in[5];
    const int nnodes = in_sizes[0] / 64;

    prep_kernel<<<32, 256>>>(w000, w101, w110, w112);

    cudaFuncSetAttribute(tsq_kernel, cudaFuncAttributeMaxDynamicSharedMemorySize, SMEM_BYTES);
    const int grid = (nnodes + NODES_PER_CTA - 1) / NODES_PER_CTA;
    tsq_kernel<<<grid, NT, SMEM_BYTES>>>(nf, nm, (float*)d_out, nnodes);
}

// round 11
// speedup vs baseline: 2.1548x; 1.3467x over previous
#include <cuda_runtime.h>
#include <cuda_fp16.h>
#include <cstdint>

#define NT 256
#define NODES 64
#define AR 2064
// smem byte offsets
#define SX    0
#define SA    16384
#define SB0   148480
#define SB2A  157184
#define SB2B  161792
#define SB1   166400
#define SLUT  178688
#define SG    179232
#define SMEM_BYTES 213024
#define WT_BYTES 30752

__device__ __align__(16) char g_Wt[WT_BYTES];

__device__ __forceinline__ void decode_pair(int p, int& u, int& v) {
    int uu = 0, r = p;
    while (r >= 16 - uu) { r -= 16 - uu; ++uu; }
    u = uu; v = uu + r;
}

__global__ void prep_kernel(const float* __restrict__ w000, const float* __restrict__ w101,
                            const float* __restrict__ w110, const float* __restrict__ w112) {
    const float A000  = 0.044194173824159216f;
    const float A110  = 0.025515518153991442f;
    const float A101  = 0.0625f;
    const int tid = blockIdx.x * blockDim.x + threadIdx.x;
    const int nth = gridDim.x * blockDim.x;
    half* B0  = (half*)g_Wt;
    half* B2A = (half*)(g_Wt + 8704);
    half* B2B = (half*)(g_Wt + 13312);
    half* B1  = (half*)(g_Wt + 17920);
    unsigned* LUT = (unsigned*)(g_Wt + 30208);

    for (int idx = tid; idx < 16 * 272; idx += nth) {
        int w = idx / 272, c = idx % 272;
        int p = (c < 136) ? c : c - 136;
        int u, v; decode_pair(p, u, v);
        const float* src = (c < 136) ? w000 : w110;
        float sc = (c < 136) ? A000 : A110;
        float cc = src[u * 256 + v * 16 + w];
        if (u != v) cc += src[v * 256 + u * 16 + w];
        B0[idx] = __float2half_rn(cc * sc);
    }
    for (int idx = tid; idx < 16 * 144; idx += nth) {
        int w = idx / 144, p = idx % 144;
        float cc = 0.f;
        if (p < 136) {
            int u, v; decode_pair(p, u, v);
            cc = w112[u * 256 + v * 16 + w];
            if (u != v) cc += w112[v * 256 + u * 16 + w];
        }
        B2A[idx] = __float2half_rn(cc * A000);  // A112/sqrt(10) == A000
        B2B[idx] = __float2half_rn(cc * A110);  // A112/sqrt(30) == A110
    }
    for (int idx = tid; idx < 256 * 24; idx += nth) {
        int n = idx / 24, kk = idx % 24;
        int u = n >> 4, w = n & 15;
        float val = (kk < 16) ? w101[u * 256 + kk * 16 + w] * A101 : 0.f;
        B1[idx] = __float2half_rn(val);
    }
    for (int p = tid; p < 136; p += nth) {
        int u, v; decode_pair(p, u, v);
        LUT[p] = (unsigned)u | ((unsigned)v << 8);
    }
}

#define MMA(c, a, b) asm volatile( \
    "mma.sync.aligned.m16n8k16.row.col.f32.f16.f16.f32 " \
    "{%0,%1,%2,%3}, {%4,%5,%6,%7}, {%8,%9}, {%0,%1,%2,%3};" \
    : "+f"(c[0]), "+f"(c[1]), "+f"(c[2]), "+f"(c[3]) \
    : "r"(a[0]), "r"(a[1]), "r"(a[2]), "r"(a[3]), "r"(b[0]), "r"(b[1]))

__global__ void __launch_bounds__(NT)
tsq_kernel(const float* __restrict__ nf, const float* __restrict__ nm,
           float* __restrict__ out, int nnodes) {
    extern __shared__ char sm[];
    const int t = threadIdx.x;
    const int nodeBase = blockIdx.x * NODES;

    // stage weights/LUT (g_Wt -> SB0..SLUT contiguous)
    {
        const uint4* src = (const uint4*)g_Wt;
        uint4* dst = (uint4*)(sm + SB0);
        for (int i = t; i < WT_BYTES / 16; i += NT) dst[i] = src[i];
    }
    // zero A
    {
        uint4 z = make_uint4(0, 0, 0, 0);
        uint4* a4 = (uint4*)(sm + SA);
        for (int i = t; i < NODES * AR / 16; i += NT) a4[i] = z;
    }
    // stage x = nf+nm into float4 sX[node][u] = {x0[u], x1[u][0..2]}
    {
        const float4* a4 = (const float4*)nf;
        const float4* b4 = (const float4*)nm;
        float* sx = (float*)(sm + SX);
        const int limit = nnodes * 16;
        for (int i = t; i < NODES * 16; i += NT) {
            int gi = nodeBase * 16 + i;
            float4 a = make_float4(0.f, 0.f, 0.f, 0.f), b = a;
            if (gi < limit) { a = a4[gi]; b = b4[gi]; }
            int node = i >> 4, c0 = (i & 15) << 2;
            float vals[4] = {a.x + b.x, a.y + b.y, a.z + b.z, a.w + b.w};
#pragma unroll
            for (int j = 0; j < 4; ++j) {
                int c = c0 + j, u, f;
                if (c < 16) { u = c; f = 0; }
                else { u = (c - 16) / 3; f = 1 + (c - 16) % 3; }
                sx[(node * 16 + u) * 4 + f] = vals[j];
            }
        }
    }
    __syncthreads();

    // ---- basis: 4 threads/node, each 34 pairs ----
    {
        const int node = t >> 2, q = t & 3;
        const float4* xr = (const float4*)(sm + SX) + node * 16;
        half* arow = (half*)(sm + SA + (size_t)node * AR);
        const unsigned* lut = (const unsigned*)(sm + SLUT);
        for (int p = q; p < 136; p += 4) {
            unsigned uv = lut[p];
            float4 a = xr[uv & 255], b = xr[uv >> 8];
            float y   = a.x * b.x;
            float m00 = a.y * b.y, m01 = a.y * b.z, m02 = a.y * b.w;
            float m10 = a.z * b.y, m11 = a.z * b.z, m12 = a.z * b.w;
            float m20 = a.w * b.y, m21 = a.w * b.z, m22 = a.w * b.w;
            float h = m00 + m11;
            arow[p]       = __float2half_rn(y);
            arow[136 + p] = __float2half_rn(h + m22);
            arow[272 + p] = __float2half_rn(m01 + m10);
            arow[416 + p] = __float2half_rn(m02 + m20);
            arow[560 + p] = __float2half_rn(m12 + m21);
            arow[704 + p] = __float2half_rn(m00 - m11);
            arow[848 + p] = __float2half_rn(fmaf(2.f, m22, -h));
        }
        for (int u = q; u < 16; u += 4) arow[992 + u] = __float2half_rn(xr[u].x);
    }
    __syncthreads();

    // ---- MMA phase: 8 warps: warp = (mrow 0..3) x (nhalf 0..1) ----
    {
        const int w = t >> 5, lane = t & 31;
        const int mr = (w & 3) * 16, nh = w >> 2;
        const int r0 = lane >> 2, c2 = (lane & 3) * 2;
        const char* Abase = sm + SA + (size_t)(mr + r0) * AR + c2 * 2;
        unsigned a[4], b[2];

        // G = x0 * B1^T : K=16, warp's 16 n-tiles
        {
            a[0] = *(const unsigned*)(Abase + 992 * 2);
            a[1] = *(const unsigned*)(Abase + 992 * 2 + 8 * AR);
            a[2] = *(const unsigned*)(Abase + 992 * 2 + 16);
            a[3] = *(const unsigned*)(Abase + 992 * 2 + 8 * AR + 16);
            for (int j = 0; j < 16; ++j) {
                int nt = nh * 16 + j;
                const char* bb = sm + SB1 + (size_t)(nt * 8 + r0) * 48 + c2 * 2;
                b[0] = *(const unsigned*)bb;
                b[1] = *(const unsigned*)(bb + 16);
                float c[4] = {0.f, 0.f, 0.f, 0.f};
                MMA(c, a, b);
                int ncol = nt * 8 + c2;
                half* g0 = (half*)(sm + SG + (size_t)(mr + r0) * 528 + ncol * 2);
                *(half2*)g0 = __floats2half2_rn(c[0], c[1]);
                *(half2*)(sm + SG + (size_t)(mr + r0 + 8) * 528 + ncol * 2) =
                    __floats2half2_rn(c[2], c[3]);
            }
        }
        // out0 = [y|s] * B0^T : K=272
        {
            float c[4] = {0.f, 0.f, 0.f, 0.f};
            for (int ks = 0; ks < 17; ++ks) {
                const char* ab = Abase + ks * 32;
                a[0] = *(const unsigned*)ab;
                a[1] = *(const unsigned*)(ab + 8 * AR);
                a[2] = *(const unsigned*)(ab + 16);
                a[3] = *(const unsigned*)(ab + 8 * AR + 16);
                const char* bb = sm + SB0 + (size_t)(nh * 8 + r0) * 544 + ks * 32 + c2 * 2;
                b[0] = *(const unsigned*)bb;
                b[1] = *(const unsigned*)(bb + 16);
                MMA(c, a, b);
            }
            float* d = out + (size_t)(nodeBase + mr + r0) * 144 + nh * 8 + c2;
            *(float2*)d = make_float2(c[0], c[1]);
            *(float2*)(d + 8 * 144) = make_float2(c[2], c[3]);
        }
        // out2_k = t_k * B2^T : K=144, k=0..4
        for (int k5 = 0; k5 < 5; ++k5) {
            float c[4] = {0.f, 0.f, 0.f, 0.f};
            const int sb = (k5 < 4) ? SB2A : SB2B;
            const int akc = (272 + 144 * k5) * 2;
            for (int ks = 0; ks < 9; ++ks) {
                const char* ab = Abase + akc + ks * 32;
                a[0] = *(const unsigned*)ab;
                a[1] = *(const unsigned*)(ab + 8 * AR);
                a[2] = *(const unsigned*)(ab + 16);
                a[3] = *(const unsigned*)(ab + 8 * AR + 16);
                const char* bb = sm + sb + (size_t)(nh * 8 + r0) * 288 + ks * 32 + c2 * 2;
                b[0] = *(const unsigned*)bb;
                b[1] = *(const unsigned*)(bb + 16);
                MMA(c, a, b);
            }
            int wc = nh * 8 + c2;
            float* d = out + (size_t)(nodeBase + mr + r0) * 144 + 64 + 5 * wc + k5;
            d[0] = c[0]; d[5] = c[1];
            float* d2 = d + (size_t)8 * 144;
            d2[0] = c[2]; d2[5] = c[3];
        }
    }
    __syncthreads();

    // ---- out1 scalar: 4 threads/node, thread q -> w = 4q..4q+3 ----
    {
        const int node = t >> 2, q = t & 3;
        const float4* xr = (const float4*)(sm + SX) + node * 16;
        const half* gr = (const half*)(sm + SG + (size_t)node * 528);
        float acc[12];
#pragma unroll
        for (int j = 0; j < 12; ++j) acc[j] = 0.f;
#pragma unroll 4
        for (int u = 0; u < 16; ++u) {
            float4 xv = xr[u];
            half2 g01 = *(const half2*)(gr + u * 16 + q * 4);
            half2 g23 = *(const half2*)(gr + u * 16 + q * 4 + 2);
            float2 f01 = __half22float2(g01), f23 = __half22float2(g23);
            float gv[4] = {f01.x, f01.y, f23.x, f23.y};
#pragma unroll
            for (int j = 0; j < 4; ++j) {
                acc[j * 3 + 0] = fmaf(xv.y, gv[j], acc[j * 3 + 0]);
                acc[j * 3 + 1] = fmaf(xv.z, gv[j], acc[j * 3 + 1]);
                acc[j * 3 + 2] = fmaf(xv.w, gv[j], acc[j * 3 + 2]);
            }
        }
        float* d = out + (size_t)(nodeBase + node) * 144 + 16 + 12 * q;
        *(float4*)(d + 0) = make_float4(acc[0], acc[1], acc[2],  acc[3]);
        *(float4*)(d + 4) = make_float4(acc[4], acc[5], acc[6],  acc[7]);
        *(float4*)(d + 8) = make_float4(acc[8], acc[9], acc[10], acc[11]);
    }
}

extern "C" void kernel_launch(void* const* d_in, const int* in_sizes, int n_in,
                              void* d_out, int out_size) {
    const float* nf   = (const float*)d_in[0];
    const float* nm   = (const float*)d_in[1];
    const float* w000 = (const float*)d_in[2];
    const float* w101 = (const float*)d_in[3];
    const float* w110 = (const float*)d_in[4];
    const float* w112 = (const float*)d_in[5];
    const int nnodes = in_sizes[0] / 64;

    prep_kernel<<<32, 256>>>(w000, w101, w110, w112);

    cudaFuncSetAttribute(tsq_kernel, cudaFuncAttributeMaxDynamicSharedMemorySize, SMEM_BYTES);
    const int grid = (nnodes + NODES - 1) / NODES;
    tsq_kernel<<<grid, NT, SMEM_BYTES>>>(nf, nm, (float*)d_out, nnodes);
}